// round 1
// baseline (speedup 1.0000x reference)
#include <cuda_runtime.h>
#include <math.h>

#define BATCH 64
#define SEQ   512
#define DM    512
#define NH    8
#define HD    64
#define NA    32
#define WIN   64
#define FF    2048
#define MROWS (BATCH*SEQ)     // 32768
#define MAROWS (BATCH*NA)     // 2048

// ---------------- scratch (static __device__ arrays; no allocation) ----------------
__device__ float g_qkv[(size_t)MROWS * 3 * DM];   // local qkv  (192MB)
__device__ float g_attn[(size_t)MROWS * DM];      // attention output (64MB)
__device__ float g_x1 [(size_t)MROWS * DM];       // after local residual
__device__ float g_q2 [(size_t)MROWS * DM];       // global q
__device__ float g_kv2[(size_t)MAROWS * 2 * DM];  // anchor k,v (8MB)
__device__ float g_x2 [(size_t)MROWS * DM];
__device__ float g_x3 [(size_t)MROWS * DM];
__device__ float g_h  [(size_t)MROWS * FF];       // ffn hidden (256MB)

// ---------------- SGEMM: C[M,N] = A[M,K] @ W[N,K]^T (+bias)(+res)(gelu) ----------------
// 128x128 block tile, BK=16, 256 threads, 8x8 per-thread microtile.
template<bool GELU>
__global__ __launch_bounds__(256)
void sgemm_kernel(const float* __restrict__ A, const float* __restrict__ W,
                  const float* __restrict__ bias, const float* __restrict__ res,
                  float* __restrict__ C, int M, int N, int K)
{
    __shared__ float As[16][132];
    __shared__ float Bs[16][132];
    const int bm = blockIdx.y * 128;
    const int bn = blockIdx.x * 128;
    const int t  = threadIdx.x;
    const int tx = t & 15;          // 0..15 -> n microtile
    const int ty = t >> 4;          // 0..15 -> m microtile
    const int lr = t >> 2;          // 0..63 load row
    const int lc = (t & 3) << 2;    // 0,4,8,12 load col (float4)

    const float* Ap = A + (size_t)(bm + lr) * K + lc;
    const float* Wp = W + (size_t)(bn + lr) * K + lc;

    float acc[8][8];
#pragma unroll
    for (int i = 0; i < 8; i++)
#pragma unroll
        for (int j = 0; j < 8; j++) acc[i][j] = 0.f;

    for (int k0 = 0; k0 < K; k0 += 16) {
        float4 a0 = *(const float4*)(Ap + k0);
        float4 a1 = *(const float4*)(Ap + (size_t)64 * K + k0);
        float4 b0 = *(const float4*)(Wp + k0);
        float4 b1 = *(const float4*)(Wp + (size_t)64 * K + k0);
        __syncthreads();
        As[lc+0][lr] = a0.x; As[lc+1][lr] = a0.y; As[lc+2][lr] = a0.z; As[lc+3][lr] = a0.w;
        As[lc+0][lr+64] = a1.x; As[lc+1][lr+64] = a1.y; As[lc+2][lr+64] = a1.z; As[lc+3][lr+64] = a1.w;
        Bs[lc+0][lr] = b0.x; Bs[lc+1][lr] = b0.y; Bs[lc+2][lr] = b0.z; Bs[lc+3][lr] = b0.w;
        Bs[lc+0][lr+64] = b1.x; Bs[lc+1][lr+64] = b1.y; Bs[lc+2][lr+64] = b1.z; Bs[lc+3][lr+64] = b1.w;
        __syncthreads();
#pragma unroll
        for (int kk = 0; kk < 16; kk++) {
            float4 a01 = *(const float4*)&As[kk][ty*8];
            float4 a23 = *(const float4*)&As[kk][ty*8+4];
            float4 b01 = *(const float4*)&Bs[kk][tx*8];
            float4 b23 = *(const float4*)&Bs[kk][tx*8+4];
            float af[8] = {a01.x,a01.y,a01.z,a01.w,a23.x,a23.y,a23.z,a23.w};
            float bf[8] = {b01.x,b01.y,b01.z,b01.w,b23.x,b23.y,b23.z,b23.w};
#pragma unroll
            for (int i = 0; i < 8; i++)
#pragma unroll
                for (int j = 0; j < 8; j++)
                    acc[i][j] = fmaf(af[i], bf[j], acc[i][j]);
        }
    }

#pragma unroll
    for (int i = 0; i < 8; i++) {
        const int m = bm + ty*8 + i;
        float* Crow = C + (size_t)m * N + bn + tx*8;
        const float* Rrow = res ? (res + (size_t)m * N + bn + tx*8) : nullptr;
#pragma unroll
        for (int j = 0; j < 8; j++) {
            float v = acc[i][j];
            if (bias) v += bias[bn + tx*8 + j];
            if (Rrow) v += Rrow[j];
            if (GELU) v = 0.5f * v * (1.0f + erff(v * 0.70710678118654752f));
            Crow[j] = v;
        }
    }
}

// ---------------- local windowed causal attention ----------------
// grid: (qt=8, h=8, b=64), 256 threads (8 warps). Each warp handles 8 queries.
// Query i attends keys j in [max(0,i-64), i]  (<=65 keys).
__global__ __launch_bounds__(256)
void local_attn_kernel(const float* __restrict__ qkv, float* __restrict__ out)
{
    extern __shared__ float sm[];
    float* Qs = sm;                 // 64 x 65
    float* Ks = Qs + 64 * 65;       // 128 x 65
    float* Vs = Ks + 128 * 65;      // 128 x 65
    float* Pb = Vs + 128 * 65;      // 8 x 72

    const int qt = blockIdx.x, h = blockIdx.y, b = blockIdx.z;
    const int t = threadIdx.x;
    const int q0 = qt * 64;
    const int kbase = q0 - 64;

    // load Q tile (64 rows x 64 dims)
    for (int idx = t; idx < 64 * 16; idx += 256) {
        int r = idx >> 4, c4 = (idx & 15) << 2;
        float4 v = *(const float4*)(qkv + ((size_t)(b*SEQ + q0 + r)) * (3*DM) + h*HD + c4);
        Qs[r*65+c4] = v.x; Qs[r*65+c4+1] = v.y; Qs[r*65+c4+2] = v.z; Qs[r*65+c4+3] = v.w;
    }
    // load K,V tiles (128 rows x 64 dims), rows j = kbase + r
    for (int idx = t; idx < 128 * 16; idx += 256) {
        int r = idx >> 4, c4 = (idx & 15) << 2;
        int j = kbase + r;
        if (j >= 0) {
            const float* base = qkv + ((size_t)(b*SEQ + j)) * (3*DM) + DM + h*HD + c4;
            float4 kv = *(const float4*)base;
            float4 vv = *(const float4*)(base + DM);
            Ks[r*65+c4] = kv.x; Ks[r*65+c4+1] = kv.y; Ks[r*65+c4+2] = kv.z; Ks[r*65+c4+3] = kv.w;
            Vs[r*65+c4] = vv.x; Vs[r*65+c4+1] = vv.y; Vs[r*65+c4+2] = vv.z; Vs[r*65+c4+3] = vv.w;
        }
    }
    __syncthreads();

    const int warp = t >> 5, lane = t & 31;
    float* pw = Pb + warp * 72;

    for (int iq = warp * 8; iq < warp * 8 + 8; iq++) {
        const int i = q0 + iq;
        const int j0 = max(0, i - WIN);
        const int nk = i - j0 + 1;

        float sc[3];
        float smax = -1e30f;
        int cnt = 0;
        const float* qr = Qs + iq * 65;
        for (int jj = lane; jj < nk; jj += 32) {
            const float* kr = Ks + (j0 + jj - kbase) * 65;
            float s = 0.f;
#pragma unroll
            for (int d = 0; d < 64; d++) s = fmaf(qr[d], kr[d], s);
            s *= 0.125f;
            sc[cnt++] = s;
            smax = fmaxf(smax, s);
        }
#pragma unroll
        for (int o = 16; o; o >>= 1) smax = fmaxf(smax, __shfl_xor_sync(0xffffffffu, smax, o));

        float ssum = 0.f;
        cnt = 0;
        for (int jj = lane; jj < nk; jj += 32) {
            float e = expf(sc[cnt++] - smax);
            pw[jj] = e;
            ssum += e;
        }
#pragma unroll
        for (int o = 16; o; o >>= 1) ssum += __shfl_xor_sync(0xffffffffu, ssum, o);
        __syncwarp();

        float o0 = 0.f, o1 = 0.f;
        for (int jj = 0; jj < nk; jj++) {
            float p = pw[jj];
            const float* vr = Vs + (j0 + jj - kbase) * 65;
            o0 = fmaf(p, vr[lane], o0);
            o1 = fmaf(p, vr[lane + 32], o1);
        }
        float inv = 1.0f / ssum;
        float* dst = out + ((size_t)(b*SEQ + i)) * DM + h*HD;
        dst[lane]      = o0 * inv;
        dst[lane + 32] = o1 * inv;
        __syncwarp();
    }
}

// ---------------- global attention vs 32 anchors (no mask) ----------------
__global__ __launch_bounds__(256)
void global_attn_kernel(const float* __restrict__ q, const float* __restrict__ kv,
                        float* __restrict__ out)
{
    __shared__ float Qs[64 * 65];
    __shared__ float Ks[32 * 65];
    __shared__ float Vs[32 * 65];
    __shared__ float Pb[8][36];

    const int qt = blockIdx.x, h = blockIdx.y, b = blockIdx.z;
    const int t = threadIdx.x;
    const int q0 = qt * 64;

    for (int idx = t; idx < 64 * 16; idx += 256) {
        int r = idx >> 4, c4 = (idx & 15) << 2;
        float4 v = *(const float4*)(q + ((size_t)(b*SEQ + q0 + r)) * DM + h*HD + c4);
        Qs[r*65+c4] = v.x; Qs[r*65+c4+1] = v.y; Qs[r*65+c4+2] = v.z; Qs[r*65+c4+3] = v.w;
    }
    for (int idx = t; idx < 32 * 16; idx += 256) {
        int r = idx >> 4, c4 = (idx & 15) << 2;
        const float* base = kv + ((size_t)(b*NA + r)) * (2*DM) + h*HD + c4;
        float4 kk = *(const float4*)base;
        float4 vv = *(const float4*)(base + DM);
        Ks[r*65+c4] = kk.x; Ks[r*65+c4+1] = kk.y; Ks[r*65+c4+2] = kk.z; Ks[r*65+c4+3] = kk.w;
        Vs[r*65+c4] = vv.x; Vs[r*65+c4+1] = vv.y; Vs[r*65+c4+2] = vv.z; Vs[r*65+c4+3] = vv.w;
    }
    __syncthreads();

    const int warp = t >> 5, lane = t & 31;
    for (int iq = warp * 8; iq < warp * 8 + 8; iq++) {
        const float* qr = Qs + iq * 65;
        const float* kr = Ks + lane * 65;
        float s = 0.f;
#pragma unroll
        for (int d = 0; d < 64; d++) s = fmaf(qr[d], kr[d], s);
        s *= 0.125f;
        float smax = s;
#pragma unroll
        for (int o = 16; o; o >>= 1) smax = fmaxf(smax, __shfl_xor_sync(0xffffffffu, smax, o));
        float e = expf(s - smax);
        float ssum = e;
#pragma unroll
        for (int o = 16; o; o >>= 1) ssum += __shfl_xor_sync(0xffffffffu, ssum, o);
        Pb[warp][lane] = e;
        __syncwarp();

        float o0 = 0.f, o1 = 0.f;
#pragma unroll
        for (int j = 0; j < 32; j++) {
            float p = Pb[warp][j];
            o0 = fmaf(p, Vs[j*65 + lane], o0);
            o1 = fmaf(p, Vs[j*65 + lane + 32], o1);
        }
        float inv = 1.0f / ssum;
        float* dst = out + ((size_t)(b*SEQ + q0 + iq)) * DM + h*HD;
        dst[lane]      = o0 * inv;
        dst[lane + 32] = o1 * inv;
        __syncwarp();
    }
}

// ---------------- layernorm (one 128-thread block per row of 512) ----------------
__global__ __launch_bounds__(128)
void ln_kernel(const float* __restrict__ x, const float* __restrict__ g,
               const float* __restrict__ be, float* __restrict__ out)
{
    __shared__ float red[8];
    const int row = blockIdx.x;
    const int t = threadIdx.x;
    float4 v = ((const float4*)(x + (size_t)row * DM))[t];
    float s  = v.x + v.y + v.z + v.w;
    float ss = v.x*v.x + v.y*v.y + v.z*v.z + v.w*v.w;
#pragma unroll
    for (int o = 16; o; o >>= 1) {
        s  += __shfl_xor_sync(0xffffffffu, s, o);
        ss += __shfl_xor_sync(0xffffffffu, ss, o);
    }
    const int warp = t >> 5, lane = t & 31;
    if (lane == 0) { red[warp] = s; red[warp + 4] = ss; }
    __syncthreads();
    if (t == 0) {
        red[0] = red[0] + red[1] + red[2] + red[3];
        red[4] = red[4] + red[5] + red[6] + red[7];
    }
    __syncthreads();
    float mu  = red[0] * (1.0f / DM);
    float var = red[4] * (1.0f / DM) - mu * mu;
    float inv = rsqrtf(var + 1e-5f);
    float4 gg = ((const float4*)g)[t];
    float4 bb = ((const float4*)be)[t];
    float4 o;
    o.x = (v.x - mu) * inv * gg.x + bb.x;
    o.y = (v.y - mu) * inv * gg.y + bb.y;
    o.z = (v.z - mu) * inv * gg.z + bb.z;
    o.w = (v.w - mu) * inv * gg.w + bb.w;
    ((float4*)(out + (size_t)row * DM))[t] = o;
}

// ---------------- launch ----------------
extern "C" void kernel_launch(void* const* d_in, const int* in_sizes, int n_in,
                              void* d_out, int out_size)
{
    const float* x      = (const float*)d_in[0];
    const float* anchors= (const float*)d_in[1];
    const float* lw_in  = (const float*)d_in[2];
    const float* lb_in  = (const float*)d_in[3];
    const float* lw_out = (const float*)d_in[4];
    const float* lb_out = (const float*)d_in[5];
    const float* gw_in  = (const float*)d_in[6];
    const float* gb_in  = (const float*)d_in[7];
    const float* gw_out = (const float*)d_in[8];
    const float* gb_out = (const float*)d_in[9];
    const float* w1     = (const float*)d_in[10];
    const float* b1     = (const float*)d_in[11];
    const float* w2     = (const float*)d_in[12];
    const float* b2     = (const float*)d_in[13];
    const float* g1     = (const float*)d_in[14];
    const float* be1    = (const float*)d_in[15];
    const float* g2     = (const float*)d_in[16];
    const float* be2    = (const float*)d_in[17];
    float* out = (float*)d_out;

    float *qkv, *attn, *x1, *q2, *kv2, *x2, *x3, *hbuf;
    cudaGetSymbolAddress((void**)&qkv,  g_qkv);
    cudaGetSymbolAddress((void**)&attn, g_attn);
    cudaGetSymbolAddress((void**)&x1,   g_x1);
    cudaGetSymbolAddress((void**)&q2,   g_q2);
    cudaGetSymbolAddress((void**)&kv2,  g_kv2);
    cudaGetSymbolAddress((void**)&x2,   g_x2);
    cudaGetSymbolAddress((void**)&x3,   g_x3);
    cudaGetSymbolAddress((void**)&hbuf, g_h);

    const int smem_local = (64*65 + 128*65 + 128*65 + 8*72) * (int)sizeof(float);
    cudaFuncSetAttribute(local_attn_kernel, cudaFuncAttributeMaxDynamicSharedMemorySize, smem_local);

    dim3 thr(256);

    // 1. local QKV projection: [32768,1536]
    sgemm_kernel<false><<<dim3(1536/128, MROWS/128), thr>>>(x, lw_in, lb_in, nullptr, qkv, MROWS, 3*DM, DM);
    // 2. windowed causal attention
    local_attn_kernel<<<dim3(SEQ/64, NH, BATCH), thr, smem_local>>>(qkv, attn);
    // 3. local out-proj + residual(x) -> x1
    sgemm_kernel<false><<<dim3(DM/128, MROWS/128), thr>>>(attn, lw_out, lb_out, x, x1, MROWS, DM, DM);
    // 4. global q projection of x1
    sgemm_kernel<false><<<dim3(DM/128, MROWS/128), thr>>>(x1, gw_in, gb_in, nullptr, q2, MROWS, DM, DM);
    // 5. anchor k,v projection: [2048,1024]
    sgemm_kernel<false><<<dim3(1024/128, MAROWS/128), thr>>>(anchors, gw_in + 512*512, gb_in + 512, nullptr, kv2, MAROWS, 2*DM, DM);
    // 6. global attention (32 keys)
    global_attn_kernel<<<dim3(SEQ/64, NH, BATCH), thr>>>(q2, kv2, attn);
    // 7. global out-proj + residual(x1) -> x2
    sgemm_kernel<false><<<dim3(DM/128, MROWS/128), thr>>>(attn, gw_out, gb_out, x1, x2, MROWS, DM, DM);
    // 8. LN1 -> x3
    ln_kernel<<<MROWS, 128>>>(x2, g1, be1, x3);
    // 9. FFN1 + exact GELU: [32768,2048]
    sgemm_kernel<true><<<dim3(FF/128, MROWS/128), thr>>>(x3, w1, b1, nullptr, hbuf, MROWS, FF, DM);
    // 10. FFN2 + residual(x3) -> x2
    sgemm_kernel<false><<<dim3(DM/128, MROWS/128), thr>>>(hbuf, w2, b2, x3, x2, MROWS, DM, FF);
    // 11. LN2 -> out
    ln_kernel<<<MROWS, 128>>>(x2, g2, be2, out);
}

// round 3
// speedup vs baseline: 2.2451x; 2.2451x over previous
#include <cuda_runtime.h>
#include <math.h>
#include <stdint.h>

#define BATCH 64
#define SEQ   512
#define DM    512
#define NH    8
#define HD    64
#define NA    32
#define WIN   64
#define FF    2048
#define MROWS (BATCH*SEQ)     // 32768
#define MAROWS (BATCH*NA)     // 2048

// ---------------- scratch (static __device__ arrays; no allocation) ----------------
__device__ float g_qkv[(size_t)MROWS * 3 * DM];
__device__ float g_attn[(size_t)MROWS * DM];
__device__ float g_x1 [(size_t)MROWS * DM];
__device__ float g_q2 [(size_t)MROWS * DM];
__device__ float g_kv2[(size_t)MAROWS * 2 * DM];
__device__ float g_x2 [(size_t)MROWS * DM];
__device__ float g_x3 [(size_t)MROWS * DM];
__device__ float g_h  [(size_t)MROWS * FF];
// tf32-rounded weights, packed
#define OFF_LWIN  0
#define OFF_LWOUT (786432)
#define OFF_GWIN  (786432 + 262144)
#define OFF_GWOUT (786432 + 262144 + 786432)
#define OFF_W1    (786432 + 262144 + 786432 + 262144)
#define OFF_W2    (OFF_W1 + 1048576)
__device__ float g_wtf[(size_t)OFF_W2 + 1048576];

// ================= helpers =================
__device__ __forceinline__ uint32_t smem_u32(const void* p) {
    uint32_t a;
    asm("{ .reg .u64 t; cvta.to.shared.u64 t, %1; cvt.u32.u64 %0, t; }" : "=r"(a) : "l"(p));
    return a;
}
__device__ __forceinline__ uint32_t f2tf(float x) {
    uint32_t r;
    asm("cvt.rna.tf32.f32 %0, %1;" : "=r"(r) : "f"(x));
    return r;
}
__device__ __forceinline__ void mma8(float* c, const uint32_t* a, const uint32_t* b) {
    asm volatile(
        "mma.sync.aligned.m16n8k8.row.col.f32.tf32.tf32.f32 "
        "{%0,%1,%2,%3}, {%4,%5,%6,%7}, {%8,%9}, {%0,%1,%2,%3};"
        : "+f"(c[0]), "+f"(c[1]), "+f"(c[2]), "+f"(c[3])
        : "r"(a[0]), "r"(a[1]), "r"(a[2]), "r"(a[3]),
          "r"(b[0]), "r"(b[1]));
}
#define CP_ASYNC16(dst, src) \
    asm volatile("cp.async.cg.shared.global [%0], [%1], 16;" :: "r"(dst), "l"(src) : "memory")
#define CP_COMMIT() asm volatile("cp.async.commit_group;" ::: "memory")
#define CP_WAIT0()  asm volatile("cp.async.wait_group 0;" ::: "memory")

// ---------------- weight tf32 pre-convert ----------------
__global__ __launch_bounds__(256)
void cvt_kernel(const float* __restrict__ src, float* __restrict__ dst, int n4)
{
    int i = blockIdx.x * 256 + threadIdx.x;
    if (i < n4) {
        float4 v = ((const float4*)src)[i];
        float4 o;
        o.x = __uint_as_float(f2tf(v.x));
        o.y = __uint_as_float(f2tf(v.y));
        o.z = __uint_as_float(f2tf(v.z));
        o.w = __uint_as_float(f2tf(v.w));
        ((float4*)dst)[i] = o;
    }
}

// ================= tf32 mma.sync GEMM =================
// C[M,N] = A[M,K] @ W[N,K]^T (+bias)(+res)(gelu)
// CTA tile 128(M) x 256(N), BK=32, 256 threads, warp tile 64x64 (2x4 warps).
// A: LDG->reg->cvt.rna->STS, double-buffered. B(weights, pre-tf32): cp.async.
#define ASTRIDE 36
#define A_TILE_F (128 * ASTRIDE)   // 4608 floats
#define B_TILE_F (256 * ASTRIDE)   // 9216 floats
#define GEMM_SMEM_F (2 * A_TILE_F + 2 * B_TILE_F)   // 27648 floats = 108KB

template<bool GELU>
__global__ __launch_bounds__(256, 1)
void gemm_mma(const float* __restrict__ A, const float* __restrict__ W,
              const float* __restrict__ bias, const float* __restrict__ res,
              float* __restrict__ C, int M, int N, int K)
{
    extern __shared__ float sm[];
    float* As[2] = { sm, sm + A_TILE_F };
    float* Bs[2] = { sm + 2 * A_TILE_F, sm + 2 * A_TILE_F + B_TILE_F };

    const int t = threadIdx.x;
    const int wid = t >> 5, lane = t & 31;
    const int gid = lane >> 2, tig = lane & 3;
    const int wm = wid >> 2;            // 0..1
    const int wn = wid & 3;             // 0..3
    const int bm = blockIdx.y * 128;
    const int bn = blockIdx.x * 256;

    const int ar = t >> 3;              // 0..31
    const int ac = (t & 7) << 2;        // 0,4,..,28

    const float* Abase = A + (size_t)(bm + ar) * K + ac;
    const float* Wbase = W + (size_t)(bn + ar) * K + ac;

    float acc[4][8][4];
#pragma unroll
    for (int i = 0; i < 4; i++)
#pragma unroll
        for (int j = 0; j < 8; j++)
#pragma unroll
            for (int q = 0; q < 4; q++) acc[i][j][q] = 0.f;

    const int KT = K >> 5;

    // ---- prologue: tile 0 ----
    {
        float4 av[4];
#pragma unroll
        for (int i = 0; i < 4; i++)
            av[i] = *(const float4*)(Abase + (size_t)(i * 32) * K);
        uint32_t bdst = smem_u32(Bs[0]) + (uint32_t)(ar * ASTRIDE + ac) * 4u;
#pragma unroll
        for (int i = 0; i < 8; i++)
            CP_ASYNC16(bdst + (uint32_t)(i * 32 * ASTRIDE * 4), Wbase + (size_t)(i * 32) * K);
        CP_COMMIT();
#pragma unroll
        for (int i = 0; i < 4; i++) {
            uint32_t* d = (uint32_t*)(As[0] + (ar + i * 32) * ASTRIDE + ac);
            d[0] = f2tf(av[i].x); d[1] = f2tf(av[i].y);
            d[2] = f2tf(av[i].z); d[3] = f2tf(av[i].w);
        }
        CP_WAIT0();
        __syncthreads();
    }

    for (int kt = 0; kt < KT; kt++) {
        const int buf = kt & 1;
        const bool more = (kt + 1) < KT;
        float4 av[4];
        if (more) {
            const float* Ap = Abase + (size_t)(kt + 1) * 32;
            const float* Wp = Wbase + (size_t)(kt + 1) * 32;
#pragma unroll
            for (int i = 0; i < 4; i++)
                av[i] = *(const float4*)(Ap + (size_t)(i * 32) * K);
            uint32_t bdst = smem_u32(Bs[buf ^ 1]) + (uint32_t)(ar * ASTRIDE + ac) * 4u;
#pragma unroll
            for (int i = 0; i < 8; i++)
                CP_ASYNC16(bdst + (uint32_t)(i * 32 * ASTRIDE * 4), Wp + (size_t)(i * 32) * K);
            CP_COMMIT();
        }

        const float* Ab = As[buf];
        const float* Bb = Bs[buf];
#pragma unroll
        for (int kk = 0; kk < 4; kk++) {
            uint32_t a[4][4], b[8][2];
#pragma unroll
            for (int i = 0; i < 4; i++) {
                int m = wm * 64 + i * 16 + gid;
                const uint32_t* row = (const uint32_t*)(Ab + m * ASTRIDE + kk * 8);
                a[i][0] = row[tig];
                a[i][1] = *(const uint32_t*)(Ab + (m + 8) * ASTRIDE + kk * 8 + tig);
                a[i][2] = row[tig + 4];
                a[i][3] = *(const uint32_t*)(Ab + (m + 8) * ASTRIDE + kk * 8 + tig + 4);
            }
#pragma unroll
            for (int j = 0; j < 8; j++) {
                int n = wn * 64 + j * 8 + gid;
                const uint32_t* row = (const uint32_t*)(Bb + n * ASTRIDE + kk * 8);
                b[j][0] = row[tig];
                b[j][1] = row[tig + 4];
            }
#pragma unroll
            for (int i = 0; i < 4; i++)
#pragma unroll
                for (int j = 0; j < 8; j++)
                    mma8(acc[i][j], a[i], b[j]);
        }

        if (more) {
#pragma unroll
            for (int i = 0; i < 4; i++) {
                uint32_t* d = (uint32_t*)(As[buf ^ 1] + (ar + i * 32) * ASTRIDE + ac);
                d[0] = f2tf(av[i].x); d[1] = f2tf(av[i].y);
                d[2] = f2tf(av[i].z); d[3] = f2tf(av[i].w);
            }
            CP_WAIT0();
        }
        __syncthreads();
    }

    // ---- epilogue ----
#pragma unroll
    for (int j = 0; j < 8; j++) {
        const int gc = bn + wn * 64 + j * 8 + 2 * tig;
        const float2 bia = *(const float2*)(bias + gc);
#pragma unroll
        for (int i = 0; i < 4; i++) {
            const int gr = bm + wm * 64 + i * 16 + gid;
            float2 v0, v1;
            v0.x = acc[i][j][0] + bia.x; v0.y = acc[i][j][1] + bia.y;
            v1.x = acc[i][j][2] + bia.x; v1.y = acc[i][j][3] + bia.y;
            if (res) {
                float2 r0 = *(const float2*)(res + (size_t)gr * N + gc);
                float2 r1 = *(const float2*)(res + (size_t)(gr + 8) * N + gc);
                v0.x += r0.x; v0.y += r0.y; v1.x += r1.x; v1.y += r1.y;
            }
            if (GELU) {
                v0.x = 0.5f * v0.x * (1.0f + erff(v0.x * 0.70710678118654752f));
                v0.y = 0.5f * v0.y * (1.0f + erff(v0.y * 0.70710678118654752f));
                v1.x = 0.5f * v1.x * (1.0f + erff(v1.x * 0.70710678118654752f));
                v1.y = 0.5f * v1.y * (1.0f + erff(v1.y * 0.70710678118654752f));
            }
            *(float2*)(C + (size_t)gr * N + gc) = v0;
            *(float2*)(C + (size_t)(gr + 8) * N + gc) = v1;
        }
    }
}

// ---------------- local windowed causal attention ----------------
__global__ __launch_bounds__(256)
void local_attn_kernel(const float* __restrict__ qkv, float* __restrict__ out)
{
    extern __shared__ float sml[];
    float* Qs = sml;
    float* Ks = Qs + 64 * 65;
    float* Vs = Ks + 128 * 65;
    float* Pb = Vs + 128 * 65;

    const int qt = blockIdx.x, h = blockIdx.y, b = blockIdx.z;
    const int t = threadIdx.x;
    const int q0 = qt * 64;
    const int kbase = q0 - 64;

    for (int idx = t; idx < 64 * 16; idx += 256) {
        int r = idx >> 4, c4 = (idx & 15) << 2;
        float4 v = *(const float4*)(qkv + ((size_t)(b*SEQ + q0 + r)) * (3*DM) + h*HD + c4);
        Qs[r*65+c4] = v.x; Qs[r*65+c4+1] = v.y; Qs[r*65+c4+2] = v.z; Qs[r*65+c4+3] = v.w;
    }
    for (int idx = t; idx < 128 * 16; idx += 256) {
        int r = idx >> 4, c4 = (idx & 15) << 2;
        int j = kbase + r;
        if (j >= 0) {
            const float* base = qkv + ((size_t)(b*SEQ + j)) * (3*DM) + DM + h*HD + c4;
            float4 kv = *(const float4*)base;
            float4 vv = *(const float4*)(base + DM);
            Ks[r*65+c4] = kv.x; Ks[r*65+c4+1] = kv.y; Ks[r*65+c4+2] = kv.z; Ks[r*65+c4+3] = kv.w;
            Vs[r*65+c4] = vv.x; Vs[r*65+c4+1] = vv.y; Vs[r*65+c4+2] = vv.z; Vs[r*65+c4+3] = vv.w;
        }
    }
    __syncthreads();

    const int warp = t >> 5, lane = t & 31;
    float* pw = Pb + warp * 72;

    for (int iq = warp * 8; iq < warp * 8 + 8; iq++) {
        const int i = q0 + iq;
        const int j0 = max(0, i - WIN);
        const int nk = i - j0 + 1;

        float sc[3];
        float smax = -1e30f;
        int cnt = 0;
        const float* qr = Qs + iq * 65;
        for (int jj = lane; jj < nk; jj += 32) {
            const float* kr = Ks + (j0 + jj - kbase) * 65;
            float s = 0.f;
#pragma unroll
            for (int d = 0; d < 64; d++) s = fmaf(qr[d], kr[d], s);
            s *= 0.125f;
            sc[cnt++] = s;
            smax = fmaxf(smax, s);
        }
#pragma unroll
        for (int o = 16; o; o >>= 1) smax = fmaxf(smax, __shfl_xor_sync(0xffffffffu, smax, o));

        float ssum = 0.f;
        cnt = 0;
        for (int jj = lane; jj < nk; jj += 32) {
            float e = expf(sc[cnt++] - smax);
            pw[jj] = e;
            ssum += e;
        }
#pragma unroll
        for (int o = 16; o; o >>= 1) ssum += __shfl_xor_sync(0xffffffffu, ssum, o);
        __syncwarp();

        float o0 = 0.f, o1 = 0.f;
        for (int jj = 0; jj < nk; jj++) {
            float p = pw[jj];
            const float* vr = Vs + (j0 + jj - kbase) * 65;
            o0 = fmaf(p, vr[lane], o0);
            o1 = fmaf(p, vr[lane + 32], o1);
        }
        float inv = 1.0f / ssum;
        float* dst = out + ((size_t)(b*SEQ + i)) * DM + h*HD;
        dst[lane]      = o0 * inv;
        dst[lane + 32] = o1 * inv;
        __syncwarp();
    }
}

// ---------------- global attention vs 32 anchors ----------------
__global__ __launch_bounds__(256)
void global_attn_kernel(const float* __restrict__ q, const float* __restrict__ kv,
                        float* __restrict__ out)
{
    __shared__ float Qs[64 * 65];
    __shared__ float Ks[32 * 65];
    __shared__ float Vs[32 * 65];
    __shared__ float Pb[8][36];

    const int qt = blockIdx.x, h = blockIdx.y, b = blockIdx.z;
    const int t = threadIdx.x;
    const int q0 = qt * 64;

    for (int idx = t; idx < 64 * 16; idx += 256) {
        int r = idx >> 4, c4 = (idx & 15) << 2;
        float4 v = *(const float4*)(q + ((size_t)(b*SEQ + q0 + r)) * DM + h*HD + c4);
        Qs[r*65+c4] = v.x; Qs[r*65+c4+1] = v.y; Qs[r*65+c4+2] = v.z; Qs[r*65+c4+3] = v.w;
    }
    for (int idx = t; idx < 32 * 16; idx += 256) {
        int r = idx >> 4, c4 = (idx & 15) << 2;
        const float* base = kv + ((size_t)(b*NA + r)) * (2*DM) + h*HD + c4;
        float4 kk = *(const float4*)base;
        float4 vv = *(const float4*)(base + DM);
        Ks[r*65+c4] = kk.x; Ks[r*65+c4+1] = kk.y; Ks[r*65+c4+2] = kk.z; Ks[r*65+c4+3] = kk.w;
        Vs[r*65+c4] = vv.x; Vs[r*65+c4+1] = vv.y; Vs[r*65+c4+2] = vv.z; Vs[r*65+c4+3] = vv.w;
    }
    __syncthreads();

    const int warp = t >> 5, lane = t & 31;
    for (int iq = warp * 8; iq < warp * 8 + 8; iq++) {
        const float* qr = Qs + iq * 65;
        const float* kr = Ks + lane * 65;
        float s = 0.f;
#pragma unroll
        for (int d = 0; d < 64; d++) s = fmaf(qr[d], kr[d], s);
        s *= 0.125f;
        float smax = s;
#pragma unroll
        for (int o = 16; o; o >>= 1) smax = fmaxf(smax, __shfl_xor_sync(0xffffffffu, smax, o));
        float e = expf(s - smax);
        float ssum = e;
#pragma unroll
        for (int o = 16; o; o >>= 1) ssum += __shfl_xor_sync(0xffffffffu, ssum, o);
        Pb[warp][lane] = e;
        __syncwarp();

        float o0 = 0.f, o1 = 0.f;
#pragma unroll
        for (int j = 0; j < 32; j++) {
            float p = Pb[warp][j];
            o0 = fmaf(p, Vs[j*65 + lane], o0);
            o1 = fmaf(p, Vs[j*65 + lane + 32], o1);
        }
        float inv = 1.0f / ssum;
        float* dst = out + ((size_t)(b*SEQ + q0 + iq)) * DM + h*HD;
        dst[lane]      = o0 * inv;
        dst[lane + 32] = o1 * inv;
        __syncwarp();
    }
}

// ---------------- layernorm ----------------
__global__ __launch_bounds__(128)
void ln_kernel(const float* __restrict__ x, const float* __restrict__ g,
               const float* __restrict__ be, float* __restrict__ out)
{
    __shared__ float red[8];
    const int row = blockIdx.x;
    const int t = threadIdx.x;
    float4 v = ((const float4*)(x + (size_t)row * DM))[t];
    float s  = v.x + v.y + v.z + v.w;
    float ss = v.x*v.x + v.y*v.y + v.z*v.z + v.w*v.w;
#pragma unroll
    for (int o = 16; o; o >>= 1) {
        s  += __shfl_xor_sync(0xffffffffu, s, o);
        ss += __shfl_xor_sync(0xffffffffu, ss, o);
    }
    const int warp = t >> 5, lane = t & 31;
    if (lane == 0) { red[warp] = s; red[warp + 4] = ss; }
    __syncthreads();
    if (t == 0) {
        red[0] = red[0] + red[1] + red[2] + red[3];
        red[4] = red[4] + red[5] + red[6] + red[7];
    }
    __syncthreads();
    float mu  = red[0] * (1.0f / DM);
    float var = red[4] * (1.0f / DM) - mu * mu;
    float inv = rsqrtf(var + 1e-5f);
    float4 gg = ((const float4*)g)[t];
    float4 bb = ((const float4*)be)[t];
    float4 o;
    o.x = (v.x - mu) * inv * gg.x + bb.x;
    o.y = (v.y - mu) * inv * gg.y + bb.y;
    o.z = (v.z - mu) * inv * gg.z + bb.z;
    o.w = (v.w - mu) * inv * gg.w + bb.w;
    ((float4*)(out + (size_t)row * DM))[t] = o;
}

// ---------------- launch ----------------
extern "C" void kernel_launch(void* const* d_in, const int* in_sizes, int n_in,
                              void* d_out, int out_size)
{
    const float* x      = (const float*)d_in[0];
    const float* anchors= (const float*)d_in[1];
    const float* lw_in  = (const float*)d_in[2];
    const float* lb_in  = (const float*)d_in[3];
    const float* lw_out = (const float*)d_in[4];
    const float* lb_out = (const float*)d_in[5];
    const float* gw_in  = (const float*)d_in[6];
    const float* gb_in  = (const float*)d_in[7];
    const float* gw_out = (const float*)d_in[8];
    const float* gb_out = (const float*)d_in[9];
    const float* w1     = (const float*)d_in[10];
    const float* b1     = (const float*)d_in[11];
    const float* w2     = (const float*)d_in[12];
    const float* b2     = (const float*)d_in[13];
    const float* g1     = (const float*)d_in[14];
    const float* be1    = (const float*)d_in[15];
    const float* g2     = (const float*)d_in[16];
    const float* be2    = (const float*)d_in[17];
    float* out = (float*)d_out;

    float *qkv, *attn, *x1, *q2, *kv2, *x2, *x3, *hbuf, *wtf;
    cudaGetSymbolAddress((void**)&qkv,  g_qkv);
    cudaGetSymbolAddress((void**)&attn, g_attn);
    cudaGetSymbolAddress((void**)&x1,   g_x1);
    cudaGetSymbolAddress((void**)&q2,   g_q2);
    cudaGetSymbolAddress((void**)&kv2,  g_kv2);
    cudaGetSymbolAddress((void**)&x2,   g_x2);
    cudaGetSymbolAddress((void**)&x3,   g_x3);
    cudaGetSymbolAddress((void**)&hbuf, g_h);
    cudaGetSymbolAddress((void**)&wtf,  g_wtf);

    const int smem_local = (64*65 + 128*65 + 128*65 + 8*72) * (int)sizeof(float);
    const int gemm_smem  = GEMM_SMEM_F * (int)sizeof(float);
    cudaFuncSetAttribute(local_attn_kernel, cudaFuncAttributeMaxDynamicSharedMemorySize, smem_local);
    cudaFuncSetAttribute(gemm_mma<false>, cudaFuncAttributeMaxDynamicSharedMemorySize, gemm_smem);
    cudaFuncSetAttribute(gemm_mma<true>,  cudaFuncAttributeMaxDynamicSharedMemorySize, gemm_smem);

    dim3 thr(256);

    // 0. pre-round weights to tf32 (rna) into packed scratch
    cvt_kernel<<<(786432/4 + 255)/256, 256>>>(lw_in,  wtf + OFF_LWIN,  786432/4);
    cvt_kernel<<<(262144/4 + 255)/256, 256>>>(lw_out, wtf + OFF_LWOUT, 262144/4);
    cvt_kernel<<<(786432/4 + 255)/256, 256>>>(gw_in,  wtf + OFF_GWIN,  786432/4);
    cvt_kernel<<<(262144/4 + 255)/256, 256>>>(gw_out, wtf + OFF_GWOUT, 262144/4);
    cvt_kernel<<<(1048576/4 + 255)/256, 256>>>(w1,    wtf + OFF_W1,    1048576/4);
    cvt_kernel<<<(1048576/4 + 255)/256, 256>>>(w2,    wtf + OFF_W2,    1048576/4);

    // 1. local QKV projection: [32768,1536]
    gemm_mma<false><<<dim3(1536/256, MROWS/128), thr, gemm_smem>>>(
        x, wtf + OFF_LWIN, lb_in, nullptr, qkv, MROWS, 3*DM, DM);
    // 2. windowed causal attention
    local_attn_kernel<<<dim3(SEQ/64, NH, BATCH), thr, smem_local>>>(qkv, attn);
    // 3. local out-proj + residual(x) -> x1
    gemm_mma<false><<<dim3(DM/256, MROWS/128), thr, gemm_smem>>>(
        attn, wtf + OFF_LWOUT, lb_out, x, x1, MROWS, DM, DM);
    // 4. global q projection of x1
    gemm_mma<false><<<dim3(DM/256, MROWS/128), thr, gemm_smem>>>(
        x1, wtf + OFF_GWIN, gb_in, nullptr, q2, MROWS, DM, DM);
    // 5. anchor k,v projection: [2048,1024]
    gemm_mma<false><<<dim3(1024/256, MAROWS/128), thr, gemm_smem>>>(
        anchors, wtf + OFF_GWIN + 512*512, gb_in + 512, nullptr, kv2, MAROWS, 2*DM, DM);
    // 6. global attention (32 keys)
    global_attn_kernel<<<dim3(SEQ/64, NH, BATCH), thr>>>(q2, kv2, attn);
    // 7. global out-proj + residual(x1) -> x2
    gemm_mma<false><<<dim3(DM/256, MROWS/128), thr, gemm_smem>>>(
        attn, wtf + OFF_GWOUT, gb_out, x1, x2, MROWS, DM, DM);
    // 8. LN1 -> x3
    ln_kernel<<<MROWS, 128>>>(x2, g1, be1, x3);
    // 9. FFN1 + exact GELU: [32768,2048]
    gemm_mma<true><<<dim3(FF/256, MROWS/128), thr, gemm_smem>>>(
        x3, wtf + OFF_W1, b1, nullptr, hbuf, MROWS, FF, DM);
    // 10. FFN2 + residual(x3) -> x2
    gemm_mma<false><<<dim3(DM/256, MROWS/128), thr, gemm_smem>>>(
        hbuf, wtf + OFF_W2, b2, x3, x2, MROWS, DM, FF);
    // 11. LN2 -> out
    ln_kernel<<<MROWS, 128>>>(x2, g2, be2, out);
}